// round 1
// baseline (speedup 1.0000x reference)
#include <cuda_runtime.h>
#include <cuda_bf16.h>

// PointPillars BEV scatter, inverted as a gather:
//   1) init index grid to -1
//   2) scatter pillar ids into grid[(b*H+y)*W+x]
//   3) gather: every output element written exactly once, coalesced float4
#define BEV_H 496
#define BEV_W 432
#define BB    4
#define CC    64
#define GRID_CELLS (BB * BEV_H * BEV_W)   // 857088

__device__ int g_grid[GRID_CELLS];

__global__ void init_grid_kernel() {
    int i = blockIdx.x * blockDim.x + threadIdx.x;
    if (i < GRID_CELLS / 4) {
        reinterpret_cast<int4*>(g_grid)[i] = make_int4(-1, -1, -1, -1);
    }
}

__global__ void scatter_ids_kernel(const int* __restrict__ coords, int M) {
    int m = blockIdx.x * blockDim.x + threadIdx.x;
    if (m < M) {
        int b = coords[3 * m + 0];
        int y = coords[3 * m + 1];
        int x = coords[3 * m + 2];
        g_grid[(b * BEV_H + y) * BEV_W + x] = m;
    }
}

// Each block: one (b, y) row segment of 128 x-cells.
// Thread (xq = tid%32, cq = tid/32): 4 consecutive x cells, 4 consecutive channels.
// 4 gathered float4 loads (one per pillar row) -> 4x4 register transpose ->
// 4 coalesced STG.128 into 4 channel planes.
__global__ __launch_bounds__(512) void gather_kernel(
    const float* __restrict__ feat, float* __restrict__ out)
{
    const int b      = blockIdx.z;
    const int y      = blockIdx.y;
    const int tile_x = blockIdx.x * 128;
    const int xq     = threadIdx.x & 31;   // 0..31  -> x quad
    const int cq     = threadIdx.x >> 5;   // 0..15  -> channel quad

    __shared__ int sidx[128];
    if (threadIdx.x < 128) {
        int x = tile_x + threadIdx.x;
        sidx[threadIdx.x] = (x < BEV_W) ? g_grid[(b * BEV_H + y) * BEV_W + x] : -1;
    }
    __syncthreads();

    const int x0 = tile_x + xq * 4;
    if (x0 >= BEV_W) return;   // W=432 is a multiple of 4, so quads never straddle

    float4 v[4];
#pragma unroll
    for (int i = 0; i < 4; i++) {
        int idx = sidx[xq * 4 + i];
        if (idx >= 0) {
            v[i] = reinterpret_cast<const float4*>(feat)[(size_t)idx * (CC / 4) + cq];
        } else {
            v[i] = make_float4(0.f, 0.f, 0.f, 0.f);
        }
    }

    const int    c0    = cq * 4;
    const size_t plane = (size_t)BEV_H * BEV_W;
    size_t base = ((size_t)(b * CC + c0) * BEV_H + y) * BEV_W + x0;

    float4 o0 = make_float4(v[0].x, v[1].x, v[2].x, v[3].x);
    float4 o1 = make_float4(v[0].y, v[1].y, v[2].y, v[3].y);
    float4 o2 = make_float4(v[0].z, v[1].z, v[2].z, v[3].z);
    float4 o3 = make_float4(v[0].w, v[1].w, v[2].w, v[3].w);

    *reinterpret_cast<float4*>(out + base)             = o0;
    *reinterpret_cast<float4*>(out + base + plane)     = o1;
    *reinterpret_cast<float4*>(out + base + 2 * plane) = o2;
    *reinterpret_cast<float4*>(out + base + 3 * plane) = o3;
}

extern "C" void kernel_launch(void* const* d_in, const int* in_sizes, int n_in,
                              void* d_out, int out_size)
{
    const int*   coords = (const int*)d_in[0];    // (M, 3) int32 [b, y, x]
    const float* feat   = (const float*)d_in[1];  // (M, 64) float32
    float*       out    = (float*)d_out;          // (4, 64, 496, 432) float32

    const int M = in_sizes[0] / 3;

    // 1) grid <- -1
    {
        int n = GRID_CELLS / 4;
        init_grid_kernel<<<(n + 255) / 256, 256>>>();
    }
    // 2) grid[cell] <- pillar id (coords are collision-free by construction)
    scatter_ids_kernel<<<(M + 255) / 256, 256>>>(coords, M);
    // 3) gather into output (writes every element exactly once)
    {
        dim3 grid((BEV_W + 127) / 128, BEV_H, BB);   // (4, 496, 4)
        gather_kernel<<<grid, 512>>>(feat, out);
    }
}

// round 3
// speedup vs baseline: 1.0268x; 1.0268x over previous
#include <cuda_runtime.h>
#include <cuda_bf16.h>

// PointPillars BEV scatter, inverted as a gather with an in-block smem transpose:
//   1) init index grid to -1
//   2) scatter pillar ids into grid[(b*H+y)*W+x]
//   3) gather: coalesced feature loads (warp = 2 full pillar rows), transpose
//      through swizzled smem, coalesced float4 stores per channel plane.
#define BEV_H 496
#define BEV_W 432
#define BB    4
#define CC    64
#define GRID_CELLS (BB * BEV_H * BEV_W)   // 857088
#define TILE_X 128

__device__ int g_grid[GRID_CELLS];

__global__ void init_grid_kernel() {
    int i = blockIdx.x * blockDim.x + threadIdx.x;
    if (i < GRID_CELLS / 4) {
        reinterpret_cast<int4*>(g_grid)[i] = make_int4(-1, -1, -1, -1);
    }
}

__global__ void scatter_ids_kernel(const int* __restrict__ coords, int M) {
    int m = blockIdx.x * blockDim.x + threadIdx.x;
    if (m < M) {
        int b = coords[3 * m + 0];
        int y = coords[3 * m + 1];
        int x = coords[3 * m + 2];
        g_grid[(b * BEV_H + y) * BEV_W + x] = m;
    }
}

// smem tile: 64 channel rows x TILE_X cells, row stride 132 floats (528B, not a
// multiple of 128B -> channel rows spread across banks). x index additionally
// XOR-swizzled on bits [2:4] by (c>>3) so the reader's LDS.128 is conflict-free.
#define ROW_STRIDE 132

__global__ __launch_bounds__(512) void gather_kernel(
    const float* __restrict__ feat, float* __restrict__ out)
{
    const int b      = blockIdx.z;
    const int y      = blockIdx.y;
    const int tile_x = blockIdx.x * TILE_X;
    const int tid    = threadIdx.x;

    __shared__ int sidx[TILE_X];
    __shared__ __align__(16) float stile[CC * ROW_STRIDE];  // 33792 B

    // Stage 0: cell -> pillar id for this tile
    if (tid < TILE_X) {
        int x = tile_x + tid;
        sidx[tid] = (x < BEV_W) ? g_grid[(b * BEV_H + y) * BEV_W + x] : -1;
    }
    __syncthreads();

    // Stage 1: coalesced gather of pillar rows into smem (transposed layout).
    // Thread (p = tid&15, r = tid>>4): float4 = channels 4p..4p+3 of cell r.
    // Warp covers 2 full 256B pillar rows -> 4 lines per LDG.128 (minimal).
    {
        const int p = tid & 15;
        const int s4 = (p >> 1) << 2;        // swizzle key = (c>>3), c = 4p+j
#pragma unroll
        for (int iter = 0; iter < TILE_X / 32; iter++) {
            int rl  = iter * 32 + (tid >> 4);
            int idx = sidx[rl];
            float4 v = make_float4(0.f, 0.f, 0.f, 0.f);
            if (idx >= 0) {
                v = __ldg(reinterpret_cast<const float4*>(feat) + (size_t)idx * (CC / 4) + p);
            }
            int rx = rl ^ s4;
            stile[(4 * p + 0) * ROW_STRIDE + rx] = v.x;
            stile[(4 * p + 1) * ROW_STRIDE + rx] = v.y;
            stile[(4 * p + 2) * ROW_STRIDE + rx] = v.z;
            stile[(4 * p + 3) * ROW_STRIDE + rx] = v.w;
        }
    }
    __syncthreads();

    // Stage 2: read back as float4 over x (conflict-free LDS.128), store
    // coalesced 512B-per-warp runs into each channel plane.
    {
        const int xq = tid & 31;       // x quad within tile
        const int cq = tid >> 5;       // channel quad (uniform per warp)
        const int x0 = tile_x + 4 * xq;
        if (x0 < BEV_W) {              // W=432 is a multiple of 4
            const size_t plane = (size_t)BEV_H * BEV_W;
            size_t base = ((size_t)(b * CC + 4 * cq) * BEV_H + y) * BEV_W + x0;
#pragma unroll
            for (int j = 0; j < 4; j++) {
                int c  = 4 * cq + j;
                int s4 = ((c >> 3) & 7) << 2;
                float4 o = *reinterpret_cast<const float4*>(
                    &stile[c * ROW_STRIDE + ((4 * xq) ^ s4)]);
                __stcs(reinterpret_cast<float4*>(out + base + (size_t)j * plane), o);
            }
        }
    }
}

extern "C" void kernel_launch(void* const* d_in, const int* in_sizes, int n_in,
                              void* d_out, int out_size)
{
    const int*   coords = (const int*)d_in[0];    // (M, 3) int32 [b, y, x]
    const float* feat   = (const float*)d_in[1];  // (M, 64) float32
    float*       out    = (float*)d_out;          // (4, 64, 496, 432) float32

    const int M = in_sizes[0] / 3;

    {
        int n = GRID_CELLS / 4;
        init_grid_kernel<<<(n + 255) / 256, 256>>>();
    }
    scatter_ids_kernel<<<(M + 255) / 256, 256>>>(coords, M);
    {
        dim3 grid((BEV_W + TILE_X - 1) / TILE_X, BEV_H, BB);  // (4, 496, 4)
        gather_kernel<<<grid, 512>>>(feat, out);
    }
}

// round 4
// speedup vs baseline: 1.0508x; 1.0234x over previous
#include <cuda_runtime.h>
#include <cuda_bf16.h>

// PointPillars BEV scatter, inverted as a gather with an in-block smem transpose.
//   1) cudaMemsetAsync grid to 0xFF (-1)
//   2) scatter pillar ids into grid[(b*H+y)*W+x]
//   3) gather: coalesced feature loads (warp = 2 full pillar rows), transpose
//      through swizzled smem, coalesced float4 stores per channel plane.
//      All-empty 4-cell quads (55%) bypass smem entirely.
#define BEV_H 496
#define BEV_W 432
#define BB    4
#define CC    64
#define GRID_CELLS (BB * BEV_H * BEV_W)   // 857088
#define TILE_X 128
#define ROW_STRIDE 132

__device__ int g_grid[GRID_CELLS];

__global__ void scatter_ids_kernel(const int* __restrict__ coords, int M) {
    int m = blockIdx.x * blockDim.x + threadIdx.x;
    if (m < M) {
        int b = coords[3 * m + 0];
        int y = coords[3 * m + 1];
        int x = coords[3 * m + 2];
        g_grid[(b * BEV_H + y) * BEV_W + x] = m;
    }
}

__global__ __launch_bounds__(512) void gather_kernel(
    const float* __restrict__ feat, float* __restrict__ out)
{
    const int b      = blockIdx.z;
    const int y      = blockIdx.y;
    const int tile_x = blockIdx.x * TILE_X;
    const int tid    = threadIdx.x;

    __shared__ int sidx[TILE_X];
    __shared__ int qempty[TILE_X / 4];
    __shared__ __align__(16) float stile[CC * ROW_STRIDE];  // 33792 B

    // Stage 0: one warp loads this tile's grid row, stores sidx (int4) and
    // per-quad all-empty flags. Single __syncthreads before stage 1.
    if (tid < 32) {
        const int rowbase = (b * BEV_H + y) * BEV_W;
        const int x0 = tile_x + 4 * tid;
        int4 v;
        v.x = (x0 + 0 < BEV_W) ? g_grid[rowbase + x0 + 0] : -1;
        v.y = (x0 + 1 < BEV_W) ? g_grid[rowbase + x0 + 1] : -1;
        v.z = (x0 + 2 < BEV_W) ? g_grid[rowbase + x0 + 2] : -1;
        v.w = (x0 + 3 < BEV_W) ? g_grid[rowbase + x0 + 3] : -1;
        *reinterpret_cast<int4*>(&sidx[4 * tid]) = v;
        qempty[tid] = ((v.x & v.y & v.z & v.w) < 0) ? 1 : 0;
    }
    __syncthreads();

    // Stage 1: coalesced gather of pillar rows into transposed smem tile.
    // Thread (p = tid&15, r = tid>>4): float4 = channels 4p..4p+3 of cell r.
    // Skip smem writes for quads stage 2 will never read.
    {
        const int p  = tid & 15;
        const int s4 = (p >> 1) << 2;        // swizzle key
#pragma unroll
        for (int iter = 0; iter < TILE_X / 32; iter++) {
            int rl = iter * 32 + (tid >> 4);
            if (!qempty[rl >> 2]) {
                int idx = sidx[rl];
                float4 v = make_float4(0.f, 0.f, 0.f, 0.f);
                if (idx >= 0) {
                    v = __ldg(reinterpret_cast<const float4*>(feat)
                              + (size_t)idx * (CC / 4) + p);
                }
                int rx = rl ^ s4;
                stile[(4 * p + 0) * ROW_STRIDE + rx] = v.x;
                stile[(4 * p + 1) * ROW_STRIDE + rx] = v.y;
                stile[(4 * p + 2) * ROW_STRIDE + rx] = v.z;
                stile[(4 * p + 3) * ROW_STRIDE + rx] = v.w;
            }
        }
    }
    __syncthreads();

    // Stage 2: conflict-free LDS.128 over x (skipped for empty quads), then
    // coalesced 512B-per-warp streaming stores into each channel plane.
    {
        const int xq = tid & 31;       // x quad within tile
        const int cq = tid >> 5;       // channel quad (uniform per warp)
        const int x0 = tile_x + 4 * xq;
        if (x0 >= BEV_W) return;       // W=432 is a multiple of 4
        const bool  qe    = (qempty[xq] != 0);
        const size_t plane = (size_t)BEV_H * BEV_W;
        size_t base = ((size_t)(b * CC + 4 * cq) * BEV_H + y) * BEV_W + x0;
#pragma unroll
        for (int j = 0; j < 4; j++) {
            float4 o = make_float4(0.f, 0.f, 0.f, 0.f);
            if (!qe) {
                int c  = 4 * cq + j;
                int s4 = ((c >> 3) & 7) << 2;
                o = *reinterpret_cast<const float4*>(
                    &stile[c * ROW_STRIDE + ((4 * xq) ^ s4)]);
            }
            __stcs(reinterpret_cast<float4*>(out + base + (size_t)j * plane), o);
        }
    }
}

extern "C" void kernel_launch(void* const* d_in, const int* in_sizes, int n_in,
                              void* d_out, int out_size)
{
    const int*   coords = (const int*)d_in[0];    // (M, 3) int32 [b, y, x]
    const float* feat   = (const float*)d_in[1];  // (M, 64) float32
    float*       out    = (float*)d_out;          // (4, 64, 496, 432) float32

    const int M = in_sizes[0] / 3;

    void* grid_ptr = nullptr;
    cudaGetSymbolAddress(&grid_ptr, g_grid);
    cudaMemsetAsync(grid_ptr, 0xFF, GRID_CELLS * sizeof(int));  // all cells = -1

    scatter_ids_kernel<<<(M + 255) / 256, 256>>>(coords, M);

    dim3 grid((BEV_W + TILE_X - 1) / TILE_X, BEV_H, BB);  // (4, 496, 4)
    gather_kernel<<<grid, 512>>>(feat, out);
}